// round 12
// baseline (speedup 1.0000x reference)
#include <cuda_runtime.h>
#include <math.h>
#include <stdint.h>

// Problem constants
#define BGRAPH   256
#define M_ATOMS  48
#define NNODES   (BGRAPH * M_ATOMS)          // 12288
#define GRAPH_E  (M_ATOMS * (M_ATOMS - 1))   // 2256
#define EDGES    (BGRAPH * GRAPH_E)          // 577536
#define KRBF     32
#define NSH      25
#define FEAT     (KRBF + NSH)                // 57
#define HS       128
#define CUTOFF_INV (1.0f / 15.0f)

// Output layout (floats): feat [E,57] | node_emb [N,128] | edge_index [2,E] | transpose_index [E]
#define EMB_OFF  ((size_t)EDGES * FEAT)                 // 32,919,552
#define EI_OFF   (EMB_OFF + (size_t)NNODES * HS)        // 34,492,416
#define TR_OFF   (EI_OFF + 2 * (size_t)EDGES)           // 35,647,488

#define EDGE_BLOCKS (EDGES / 128)                        // 4512
#define EMB_BLOCKS  ((NNODES * 32) / 128)                // 3072
#define TOTAL_BLOCKS (EDGE_BLOCKS + EMB_BLOCKS)          // 7584

// L2 residency: pin ~95 MB of the 145.8 MB output (R8-validated config).
#define PIN_FEAT_BLOCKS 2800

__device__ __forceinline__ uint32_t smem_u32(const void* p) {
    uint32_t a;
    asm("{ .reg .u64 t; cvta.to.shared.u64 t, %1; cvt.u32.u64 %0, t; }" : "=r"(a) : "l"(p));
    return a;
}
__device__ __forceinline__ uint64_t policy_evict_last() {
    uint64_t pol;
    asm("createpolicy.fractional.L2::evict_last.b64 %0, 1.0;" : "=l"(pol));
    return pol;
}
__device__ __forceinline__ uint64_t policy_evict_first() {
    uint64_t pol;
    asm("createpolicy.fractional.L2::evict_first.b64 %0, 1.0;" : "=l"(pol));
    return pol;
}
__device__ __forceinline__ void stg_hint(float* p, float v, uint64_t pol) {
    asm volatile("st.global.L2::cache_hint.f32 [%0], %1, %2;"
                 :: "l"(p), "f"(v), "l"(pol) : "memory");
}
__device__ __forceinline__ void stg4_hint(float4* p, float4 v, uint64_t pol) {
    asm volatile("st.global.L2::cache_hint.v4.f32 [%0], {%1,%2,%3,%4}, %5;"
                 :: "l"(p), "f"(v.x), "f"(v.y), "f"(v.z), "f"(v.w), "l"(pol) : "memory");
}

// ---------------------------------------------------------------------------
// FMA-pipe transcendentals (keep MUFU free: only RSQ stays on MUFU).
// ---------------------------------------------------------------------------
// exp(u) for u in ~[-8, 0.5]: 2^t range reduction via magic-number rounding,
// degree-6 Taylor for 2^f on [-0.5, 0.5] (abs err ~3e-8). All FMA/ALU.
__device__ __forceinline__ float fast_exp(float u) {
    const float t = u * 1.4426950408889634f;
    const float m = t + 12582912.0f;                 // round-to-nearest (magic)
    const int   i = __float_as_int(m) - 0x4B400000;  // integer part (signed)
    const float f = t - (m - 12582912.0f);           // f in [-0.5, 0.5]
    float pf = 1.5353e-4f;                           // ln2^6/720
    pf = fmaf(pf, f, 1.3333558e-3f);                 // ln2^5/120
    pf = fmaf(pf, f, 9.6181292e-3f);                 // ln2^4/24
    pf = fmaf(pf, f, 5.5504109e-2f);                 // ln2^3/6
    pf = fmaf(pf, f, 2.4022651e-1f);                 // ln2^2/2
    pf = fmaf(pf, f, 6.9314718e-1f);                 // ln2
    pf = fmaf(pf, f, 1.0f);
    return __int_as_float(__float_as_int(pf) + (i << 23));  // pf * 2^i
}

// 1/d via bit-trick estimate + 3 Newton iterations (rel err ~1e-8 for
// well-scaled d; exact enough for ratio^31 amplification).
__device__ __forceinline__ float fast_rcp(float d) {
    float x = __int_as_float(0x7EF311C3 - __float_as_int(d));
    x = x * fmaf(-d, x, 2.0f);
    x = x * fmaf(-d, x, 2.0f);
    x = x * fmaf(-d, x, 2.0f);
    return x;
}

// ---------------------------------------------------------------------------
// Fused kernel (R8 structure: 128-thread CTAs, one block TMA flush).
//  blocks [0, 4512): 1 thread = 1 edge -> smem tile [128][57], one
//    cp.async.bulk (29184 B) per block with L2 eviction hint.
//  blocks [4512, 7584): embedding gather, 1 thread = 1 float4.
// ---------------------------------------------------------------------------
__global__ void __launch_bounds__(128) fused_kernel(
    const float*  __restrict__ pos,
    const int*    __restrict__ an,
    const float4* __restrict__ table4,
    const float*  __restrict__ alpha,
    float* __restrict__ out)
{
    __shared__ __align__(16) float tile[128 * FEAT];

    if (blockIdx.x >= EDGE_BLOCKS) {
        const int i = (blockIdx.x - EDGE_BLOCKS) * 128 + threadIdx.x; // < NNODES*32
        const int n = i >> 5;
        const int c = i & 31;
        float4* out4 = (float4*)(out + EMB_OFF);
        stg4_hint(out4 + i, table4[an[n] * 32 + c], policy_evict_last());
        return;
    }

    const int e = blockIdx.x * 128 + threadIdx.x;      // grid sized exactly

    // ---- index math ----
    const int g = e / GRAPH_E;
    const int t = e - g * GRAPH_E;
    const int s = t / (M_ATOMS - 1);
    const int k = t - s * (M_ATOMS - 1);
    const int d = k + (k >= s);
    const int src = g * M_ATOMS + s;
    const int dst = g * M_ATOMS + d;
    const int tr  = g * GRAPH_E + d * (M_ATOMS - 1) + s - (d < s);

    // ---- pos prefetch ----
    const float dx0 = __ldg(pos + dst * 3 + 0);
    const float dy0 = __ldg(pos + dst * 3 + 1);
    const float dz0 = __ldg(pos + dst * 3 + 2);
    const float sx0 = __ldg(pos + src * 3 + 0);
    const float sy0 = __ldg(pos + src * 3 + 1);
    const float sz0 = __ldg(pos + src * 3 + 2);

    // ---- index outputs (coalesced, pinned region) ----
    {
        const uint64_t pol = policy_evict_last();
        stg_hint(out + EI_OFF + e,         (float)dst, pol);
        stg_hint(out + EI_OFF + EDGES + e, (float)src, pol);
        stg_hint(out + TR_OFF + e,         (float)tr,  pol);
    }

    // ---- geometry: the ONLY MUFU op left (RSQ) ----
    const float ex = dx0 - sx0, ey = dy0 - sy0, ez = dz0 - sz0;
    float r2 = fmaxf(ex * ex + ey * ey + ez * ez, 1e-12f);
    const float rinv = rsqrtf(r2);
    const float r    = r2 * rinv;
    const float x = ex * rinv, y = ey * rinv, z = ez * rinv;

    float* row = &tile[threadIdx.x * FEAT];

    // ---- cutoff (FMA-pipe exp + NR recip) ----
    const float rc  = r * CUTOFF_INV;
    const float rc2 = rc * rc;
    const float den = fmaxf((1.0f - rc) * (1.0f + rc), 1e-9f);
    const float fcut = (rc < 1.0f) ? fast_exp(-rc2 * fast_rcp(den)) : 0.0f;

    // ---- exponential Bernstein RBF: even/odd split ratio recurrence ----
    // row[v] = fcut * C(31,v) * p^(31-v) * q^v,  p = exp(xx), q = 1-p.
    // Chain from a = max(p,q) >= 1/2; direction by binomial symmetry.
    const float aeff = 0.5f * alpha[0];
    const float xx = -aeff * r;
    const float p = fast_exp(xx);
    const float q = 1.0f - p;
    const float a = fmaxf(p, q);
    const float b = 1.0f - a;
    const float ratio  = b * fast_rcp(a);   // a in [0.5, 1]
    const float ratio2 = ratio * ratio;

    const float a2 = a * a, a4 = a2 * a2, a8 = a4 * a4, a16 = a8 * a8;
    const float seed = a16 * a8 * a4 * a2 * a * fcut;   // fcut * a^31

    const bool  up   = (p >= q);
    float* sp = row + (up ? 0 : 31);
    const int step = up ? 1 : -1;

    float ev = seed;                    // term 0
    float ov = seed * (31.0f * ratio);  // term 1
    sp[0]    = ev;
    sp[step] = ov;
#pragma unroll
    for (int j = 0; j < 15; ++j) {
        const float ce = ((float)(31 - 2*j) * (float)(30 - 2*j)) /
                         ((float)(2*j + 1) * (float)(2*j + 2));
        ev *= ratio2 * ce;
        sp[step * (2*j + 2)] = ev;
        if (j < 14) {
            const float co = ((float)(30 - 2*j) * (float)(29 - 2*j)) /
                             ((float)(2*j + 2) * (float)(2*j + 3));
            ov *= ratio2 * co;
            sp[step * (2*j + 3)] = ov;
        }
    }
    ov *= ratio2 * (2.0f / 930.0f);     // close odd chain: term 31
    sp[step * 31] = ov;

    // ---- real spherical harmonics, component-normalized, l <= 4 ----
    const float C2 = x * x - y * y,      S2 = 2.0f * x * y;
    const float C3 = C2 * x - S2 * y,    S3 = S2 * x + C2 * y;
    const float C4 = C3 * x - S3 * y,    S4 = S3 * x + C3 * y;
    const float z2 = z * z;

    const float q20 = 1.5f  * z2 - 0.5f;
    const float q30 = (2.5f * z2 - 1.5f) * z;
    const float q40 = (4.375f * z2 - 3.75f) * z2 + 0.375f;
    const float q31 = 7.5f  * z2 - 1.5f;
    const float q41 = (17.5f * z2 - 7.5f) * z;
    const float q42 = 52.5f * z2 - 7.5f;

    float* sh = row + KRBF;
    sh[0]  = 1.0f;
    sh[1]  = 1.7320508f * y;
    sh[2]  = 1.7320508f * z;
    sh[3]  = 1.7320508f * x;
    sh[4]  = 1.9364917f * S2;
    sh[5]  = 3.8729833f * y * z;
    sh[6]  = 2.2360680f * q20;
    sh[7]  = 3.8729833f * x * z;
    sh[8]  = 1.9364917f * C2;
    sh[9]  = 2.0916500f * S3;
    sh[10] = 5.1234756f * z * S2;
    sh[11] = 1.0801234f * q31 * y;
    sh[12] = 2.6457513f * q30;
    sh[13] = 1.0801234f * q31 * x;
    sh[14] = 5.1234756f * z * C2;
    sh[15] = 2.0916500f * C3;
    sh[16] = 2.2185299f * S4;
    sh[17] = 6.2749501f * z * S3;
    sh[18] = 0.2236068f * q42 * S2;
    sh[19] = 0.9486833f * q41 * y;
    sh[20] = 3.0f       * q40;
    sh[21] = 0.9486833f * q41 * x;
    sh[22] = 0.2236068f * q42 * C2;
    sh[23] = 6.2749501f * z * C3;
    sh[24] = 2.2185299f * C4;

    // ---- flush block tile (29184 B, contiguous smem AND global) ----
    __syncthreads();
    if (threadIdx.x == 0) {
        asm volatile("fence.proxy.async.shared::cta;" ::: "memory");
        float* gdst = out + (size_t)blockIdx.x * (128 * FEAT);
        const uint32_t saddr = smem_u32(tile);
        const uint64_t pol = (blockIdx.x < PIN_FEAT_BLOCKS) ? policy_evict_last()
                                                            : policy_evict_first();
        asm volatile(
            "cp.async.bulk.global.shared::cta.bulk_group.L2::cache_hint [%0], [%1], %2, %3;"
            :: "l"(gdst), "r"(saddr), "r"(128 * FEAT * 4), "l"(pol) : "memory");
        asm volatile("cp.async.bulk.commit_group;" ::: "memory");
        asm volatile("cp.async.bulk.wait_group.read 0;" ::: "memory");
    }
}

extern "C" void kernel_launch(void* const* d_in, const int* in_sizes, int n_in,
                              void* d_out, int out_size)
{
    const float* pos   = (const float*)d_in[0];
    const int*   an    = (const int*)d_in[1];
    const float* table = (const float*)d_in[2];
    const float* alpha = (const float*)d_in[3];
    float* out = (float*)d_out;

    fused_kernel<<<TOTAL_BLOCKS, 128>>>(pos, an, (const float4*)table, alpha, out);
}

// round 14
// speedup vs baseline: 1.0102x; 1.0102x over previous
#include <cuda_runtime.h>
#include <math.h>
#include <stdint.h>

// Problem constants
#define BGRAPH   256
#define M_ATOMS  48
#define NNODES   (BGRAPH * M_ATOMS)          // 12288
#define GRAPH_E  (M_ATOMS * (M_ATOMS - 1))   // 2256
#define EDGES    (BGRAPH * GRAPH_E)          // 577536
#define KRBF     32
#define NSH      25
#define FEAT     (KRBF + NSH)                // 57
#define HS       128
#define CUTOFF_INV (1.0f / 15.0f)

// Output layout (floats): feat [E,57] | node_emb [N,128] | edge_index [2,E] | transpose_index [E]
#define EMB_OFF  ((size_t)EDGES * FEAT)                 // 32,919,552
#define EI_OFF   (EMB_OFF + (size_t)NNODES * HS)        // 34,492,416
#define TR_OFF   (EI_OFF + 2 * (size_t)EDGES)           // 35,647,488

// 256-thread CTAs; edge blocks: 2 threads per edge, 128 edges per block.
#define EDGE_BLOCKS (EDGES / 128)                        // 4512
#define EMB_BLOCKS  ((NNODES * 32) / 256)                // 1536
#define TOTAL_BLOCKS (EDGE_BLOCKS + EMB_BLOCKS)          // 6048

// L2 residency: pin ~95 MB of the 145.8 MB output (R8-validated config).
#define PIN_FEAT_BLOCKS 2800

__device__ __forceinline__ uint32_t smem_u32(const void* p) {
    uint32_t a;
    asm("{ .reg .u64 t; cvta.to.shared.u64 t, %1; cvt.u32.u64 %0, t; }" : "=r"(a) : "l"(p));
    return a;
}
__device__ __forceinline__ uint64_t policy_evict_last() {
    uint64_t pol;
    asm("createpolicy.fractional.L2::evict_last.b64 %0, 1.0;" : "=l"(pol));
    return pol;
}
__device__ __forceinline__ uint64_t policy_evict_first() {
    uint64_t pol;
    asm("createpolicy.fractional.L2::evict_first.b64 %0, 1.0;" : "=l"(pol));
    return pol;
}
__device__ __forceinline__ void stg_hint(float* p, float v, uint64_t pol) {
    asm volatile("st.global.L2::cache_hint.f32 [%0], %1, %2;"
                 :: "l"(p), "f"(v), "l"(pol) : "memory");
}
__device__ __forceinline__ void stg4_hint(float4* p, float4 v, uint64_t pol) {
    asm volatile("st.global.L2::cache_hint.v4.f32 [%0], {%1,%2,%3,%4}, %5;"
                 :: "l"(p), "f"(v.x), "f"(v.y), "f"(v.z), "f"(v.w), "l"(pol) : "memory");
}

// FMA-pipe transcendentals (MUFU stays nearly idle: only RSQ).
__device__ __forceinline__ float fast_exp(float u) {
    const float t = u * 1.4426950408889634f;
    const float m = t + 12582912.0f;                 // round-to-nearest (magic)
    const int   i = __float_as_int(m) - 0x4B400000;
    const float f = t - (m - 12582912.0f);           // f in [-0.5, 0.5]
    float pf = 1.5353e-4f;
    pf = fmaf(pf, f, 1.3333558e-3f);
    pf = fmaf(pf, f, 9.6181292e-3f);
    pf = fmaf(pf, f, 5.5504109e-2f);
    pf = fmaf(pf, f, 2.4022651e-1f);
    pf = fmaf(pf, f, 6.9314718e-1f);
    pf = fmaf(pf, f, 1.0f);
    return __int_as_float(__float_as_int(pf) + (i << 23));
}
__device__ __forceinline__ float fast_rcp(float d) {
    float x = __int_as_float(0x7EF311C3 - __float_as_int(d));
    x = x * fmaf(-d, x, 2.0f);
    x = x * fmaf(-d, x, 2.0f);
    x = x * fmaf(-d, x, 2.0f);
    return x;
}

// ---------------------------------------------------------------------------
// Fused kernel, 2 threads per edge (256-thread CTAs, same 29 KB tile ->
// 56 resident warps/SM instead of 28; serial chains halved).
//  blocks [0, 4512): threads 2i,2i+1 handle edge i. Both compute geometry/
//    seed; half 0 writes even Bernstein terms + sh[0..12], half 1 writes odd
//    terms + sh[13..24]. One cp.async.bulk per block flushes [128][57].
//  blocks [4512, 6048): embedding gather, 1 thread = 1 float4.
// ---------------------------------------------------------------------------
__global__ void __launch_bounds__(256) fused_kernel(
    const float*  __restrict__ pos,
    const int*    __restrict__ an,
    const float4* __restrict__ table4,
    const float*  __restrict__ alpha,
    float* __restrict__ out)
{
    __shared__ __align__(16) float tile[128 * FEAT];

    if (blockIdx.x >= EDGE_BLOCKS) {
        const int i = (blockIdx.x - EDGE_BLOCKS) * 256 + threadIdx.x; // < NNODES*32
        const int n = i >> 5;
        const int c = i & 31;
        float4* out4 = (float4*)(out + EMB_OFF);
        stg4_hint(out4 + i, table4[an[n] * 32 + c], policy_evict_last());
        return;
    }

    const int half = threadIdx.x & 1;                  // 0: even terms, 1: odd
    const int eloc = threadIdx.x >> 1;                 // edge within block
    const int e    = blockIdx.x * 128 + eloc;

    // ---- index math (duplicated across the pair; cheap) ----
    const int g = e / GRAPH_E;
    const int t = e - g * GRAPH_E;
    const int s = t / (M_ATOMS - 1);
    const int k = t - s * (M_ATOMS - 1);
    const int d = k + (k >= s);
    const int src = g * M_ATOMS + s;
    const int dst = g * M_ATOMS + d;

    // ---- pos prefetch ----
    const float dx0 = __ldg(pos + dst * 3 + 0);
    const float dy0 = __ldg(pos + dst * 3 + 1);
    const float dz0 = __ldg(pos + dst * 3 + 2);
    const float sx0 = __ldg(pos + src * 3 + 0);
    const float sy0 = __ldg(pos + src * 3 + 1);
    const float sz0 = __ldg(pos + src * 3 + 2);

    // ---- index outputs: split across the pair ----
    {
        const uint64_t pol = policy_evict_last();
        if (half == 0) {
            stg_hint(out + EI_OFF + e,         (float)dst, pol);
            stg_hint(out + EI_OFF + EDGES + e, (float)src, pol);
        } else {
            const int tr = g * GRAPH_E + d * (M_ATOMS - 1) + s - (d < s);
            stg_hint(out + TR_OFF + e, (float)tr, pol);
        }
    }

    // ---- geometry ----
    const float ex = dx0 - sx0, ey = dy0 - sy0, ez = dz0 - sz0;
    float r2 = fmaxf(ex * ex + ey * ey + ez * ez, 1e-12f);
    const float rinv = rsqrtf(r2);
    const float r    = r2 * rinv;
    const float x = ex * rinv, y = ey * rinv, z = ez * rinv;

    float* row = &tile[eloc * FEAT];

    // ---- cutoff ----
    const float rc  = r * CUTOFF_INV;
    const float rc2 = rc * rc;
    const float den = fmaxf((1.0f - rc) * (1.0f + rc), 1e-9f);
    const float fcut = (rc < 1.0f) ? fast_exp(-rc2 * fast_rcp(den)) : 0.0f;

    // ---- exponential Bernstein RBF ----
    // term(v) = fcut * C(31,v) * a^(31-v) * b^v, a = max(p,q) >= 1/2,
    // written ascending (a==p) or descending (a==q) by binomial symmetry.
    // half 0 owns terms 0,2,...,30; half 1 owns 1,3,...,31. Each is a
    // single 15-step chain with multiplier ratio^2 * const.
    const float aeff = 0.5f * alpha[0];
    const float xx = -aeff * r;
    const float p = fast_exp(xx);
    const float q = 1.0f - p;
    const float a = fmaxf(p, q);
    const float b = 1.0f - a;
    const float ratio  = b * fast_rcp(a);
    const float ratio2 = ratio * ratio;

    const float a2 = a * a, a4 = a2 * a2, a8 = a4 * a4, a16 = a8 * a8;
    const float seed = a16 * a8 * a4 * a2 * a * fcut;   // fcut * a^31

    const bool  up   = (p >= q);
    float* sp = row + (up ? 0 : 31);
    const int step = up ? 1 : -1;

    if (half == 0) {
        float ev = seed;                        // term 0
        sp[0] = ev;
#pragma unroll
        for (int j = 0; j < 15; ++j) {          // terms 2,4,...,30
            const float ce = ((float)(31 - 2*j) * (float)(30 - 2*j)) /
                             ((float)(2*j + 1) * (float)(2*j + 2));
            ev *= ratio2 * ce;
            sp[step * (2*j + 2)] = ev;
        }
    } else {
        float ov = seed * (31.0f * ratio);      // term 1
        sp[step] = ov;
#pragma unroll
        for (int j = 0; j < 15; ++j) {          // terms 3,5,...,31
            const float co = ((float)(30 - 2*j) * (float)(29 - 2*j)) /
                             ((float)(2*j + 2) * (float)(2*j + 3));
            ov *= ratio2 * co;
            sp[step * (2*j + 3)] = ov;
        }
    }

    // ---- real spherical harmonics: split 13 / 12 across the pair ----
    const float C2 = x * x - y * y,      S2 = 2.0f * x * y;
    const float C3 = C2 * x - S2 * y,    S3 = S2 * x + C2 * y;
    const float z2 = z * z;

    float* sh = row + KRBF;
    if (half == 0) {
        const float q20 = 1.5f  * z2 - 0.5f;
        const float q30 = (2.5f * z2 - 1.5f) * z;
        const float q31 = 7.5f  * z2 - 1.5f;
        sh[0]  = 1.0f;
        sh[1]  = 1.7320508f * y;
        sh[2]  = 1.7320508f * z;
        sh[3]  = 1.7320508f * x;
        sh[4]  = 1.9364917f * S2;
        sh[5]  = 3.8729833f * y * z;
        sh[6]  = 2.2360680f * q20;
        sh[7]  = 3.8729833f * x * z;
        sh[8]  = 1.9364917f * C2;
        sh[9]  = 2.0916500f * S3;
        sh[10] = 5.1234756f * z * S2;
        sh[11] = 1.0801234f * q31 * y;
        sh[12] = 2.6457513f * q30;
    } else {
        const float C4 = C3 * x - S3 * y,  S4 = S3 * x + C3 * y;
        const float q40 = (4.375f * z2 - 3.75f) * z2 + 0.375f;
        const float q31 = 7.5f  * z2 - 1.5f;
        const float q41 = (17.5f * z2 - 7.5f) * z;
        const float q42 = 52.5f * z2 - 7.5f;
        sh[13] = 1.0801234f * q31 * x;
        sh[14] = 5.1234756f * z * C2;
        sh[15] = 2.0916500f * C3;
        sh[16] = 2.2185299f * S4;
        sh[17] = 6.2749501f * z * S3;
        sh[18] = 0.2236068f * q42 * S2;
        sh[19] = 0.9486833f * q41 * y;
        sh[20] = 3.0f       * q40;
        sh[21] = 0.9486833f * q41 * x;
        sh[22] = 0.2236068f * q42 * C2;
        sh[23] = 6.2749501f * z * C3;
        sh[24] = 2.2185299f * C4;
    }

    // ---- flush block tile (29184 B, contiguous smem AND global) ----
    __syncthreads();
    if (threadIdx.x == 0) {
        asm volatile("fence.proxy.async.shared::cta;" ::: "memory");
        float* gdst = out + (size_t)blockIdx.x * (128 * FEAT);
        const uint32_t saddr = smem_u32(tile);
        const uint64_t pol = (blockIdx.x < PIN_FEAT_BLOCKS) ? policy_evict_last()
                                                            : policy_evict_first();
        asm volatile(
            "cp.async.bulk.global.shared::cta.bulk_group.L2::cache_hint [%0], [%1], %2, %3;"
            :: "l"(gdst), "r"(saddr), "r"(128 * FEAT * 4), "l"(pol) : "memory");
        asm volatile("cp.async.bulk.commit_group;" ::: "memory");
        asm volatile("cp.async.bulk.wait_group.read 0;" ::: "memory");
    }
}

extern "C" void kernel_launch(void* const* d_in, const int* in_sizes, int n_in,
                              void* d_out, int out_size)
{
    const float* pos   = (const float*)d_in[0];
    const int*   an    = (const int*)d_in[1];
    const float* table = (const float*)d_in[2];
    const float* alpha = (const float*)d_in[3];
    float* out = (float*)d_out;

    fused_kernel<<<TOTAL_BLOCKS, 256>>>(pos, an, (const float4*)table, alpha, out);
}